// round 13
// baseline (speedup 1.0000x reference)
#include <cuda_runtime.h>
#include <cuda_bf16.h>
#include <math.h>

#define EPS 1e-9f

static constexpr int BMAX = 1024;
static constexpr int DMAX = 512;
static constexpr int UMAX = 512;

typedef unsigned long long ull;

// Scratch (device globals). d-pair-major layouts, consumed as ulonglong2:
__device__ float4 g_LN4[BMAX * DMAX / 2];        // {l0, l1, nmf0, nmf1} per (b, d-pair)
__device__ float4 g_P4 [DMAX / 2 * UMAX / 2];    // {p(d0,u0), p(d1,u0), p(d0,u1), p(d1,u1)}
__device__ float4 g_W4 [DMAX / 2 * UMAX / 2];    // same layout for w
__device__ float4 g_DW4[DMAX / 2 * UMAX / 2];    // same layout: odd(p) ? -2w : 0

// ---------------- Fused prepass (also inits out = bias) ----------------
__global__ void prep_kernel(const float* __restrict__ x,
                            const float* __restrict__ w,
                            const float* __restrict__ p,
                            const float* __restrict__ bias,
                            float* __restrict__ out,
                            int nLN4, int nPW, int nOut, int D, int U) {
    int i = blockIdx.x * blockDim.x + threadIdx.x;
    const int D2 = D >> 1, U2 = U >> 1;
    if (i < nLN4) {                       // i = b * D2 + dp
        int b  = i / D2;
        int dp = i - b * D2;
        float xe0 = x[b * D + 2 * dp]     + EPS;
        float xe1 = x[b * D + 2 * dp + 1] + EPS;
        float4 v;
        v.x = log2f(fabsf(xe0));
        v.y = log2f(fabsf(xe1));
        v.z = (xe0 < 0.f) ? 1.f : 0.f;
        v.w = (xe1 < 0.f) ? 1.f : 0.f;
        g_LN4[i] = v;
    }
    if (i < nPW) {                        // i = dp * U2 + up
        int dp = i / U2;
        int up = i - dp * U2;
        int base = (2 * dp) * U + 2 * up;
        float p00 = p[base],     p01 = p[base + 1];
        float p10 = p[base + U], p11 = p[base + U + 1];
        float w00 = w[base],     w01 = w[base + 1];
        float w10 = w[base + U], w11 = w[base + U + 1];
        g_P4[i] = make_float4(p00, p10, p01, p11);   // {d0u0, d1u0, d0u1, d1u1}
        g_W4[i] = make_float4(w00, w10, w01, w11);
        float dw00 = (fmodf(p00, 2.f) != 0.f) ? -2.f * w00 : 0.f;
        float dw10 = (fmodf(p10, 2.f) != 0.f) ? -2.f * w10 : 0.f;
        float dw01 = (fmodf(p01, 2.f) != 0.f) ? -2.f * w01 : 0.f;
        float dw11 = (fmodf(p11, 2.f) != 0.f) ? -2.f * w11 : 0.f;
        g_DW4[i] = make_float4(dw00, dw10, dw01, dw11);
    }
    if (i < nOut) out[i] = bias[i % U];
}

// One u-block (2 elems, a d-pair for one u): fully fused chain in a single asm
// scope so ptxas can coalesce the pair-split/join movs.
//   e = p .* l;  v = 2^e;  ws = nm .* dw + w;  acc += ws .* v
__device__ __forceinline__ void ublock(ull p, ull lp, ull nm, ull dw, ull w, ull& acc) {
    asm("{\n\t"
        ".reg .b64 ee, vv, ws;\n\t"
        ".reg .f32 e0, e1, v0, v1;\n\t"
        "mul.rn.f32x2 ee, %1, %2;\n\t"
        "mov.b64 {e0, e1}, ee;\n\t"
        "ex2.approx.f32 v0, e0;\n\t"
        "ex2.approx.f32 v1, e1;\n\t"
        "mov.b64 vv, {v0, v1};\n\t"
        "fma.rn.f32x2 ws, %3, %4, %5;\n\t"
        "fma.rn.f32x2 %0, ws, vv, %0;\n\t"
        "}"
        : "+l"(acc)
        : "l"(p), "l"(lp), "l"(nm), "l"(dw), "l"(w));
}

__device__ __forceinline__ void unpack2(ull p, float& a, float& b) {
    asm("mov.b64 {%0, %1}, %2;" : "=f"(a), "=f"(b) : "l"(p));
}

// ---------------- Main kernel (compile-time shapes, fully unrolled, f32x2) ----------------
static constexpr int TBT     = 8;
static constexpr int THREADS = 128;
static constexpr int DSPLIT  = 16;

template <int D, int U>
__global__ __launch_bounds__(THREADS, 7)
void power_layer_kernel(float* __restrict__ out) {
    constexpr int U2  = U / 2;        // 256 u-pairs
    constexpr int D2  = D / 2;        // 256 d-pairs
    constexpr int nDP = D2 / DSPLIT;  // 16 d-pairs per block

    const int up  = blockIdx.y * THREADS + threadIdx.x;   // u-pair index
    const int b0  = blockIdx.x * TBT;
    const int dp0 = blockIdx.z * nDP;

    // Consume the float4 tables as ulonglong2: .x = low f32x2 pair, .y = high.
    const ulonglong2* __restrict__ Pp  = (const ulonglong2*)(g_P4  + dp0 * U2 + up);
    const ulonglong2* __restrict__ Wp  = (const ulonglong2*)(g_W4  + dp0 * U2 + up);
    const ulonglong2* __restrict__ DWp = (const ulonglong2*)(g_DW4 + dp0 * U2 + up);
    const ulonglong2* __restrict__ LNp = (const ulonglong2*)(g_LN4 + (size_t)b0 * D2 + dp0);

    ull acc[TBT][2];
#pragma unroll
    for (int bb = 0; bb < TBT; bb++) { acc[bb][0] = 0ull; acc[bb][1] = 0ull; }

#pragma unroll
    for (int j = 0; j < nDP; j++) {
        // Immediate-offset LDG.128s; pairs arrive pre-packed (no MOVs).
        const ulonglong2 P  = Pp [j * U2];   // .x = {p(d0,u0),p(d1,u0)}, .y = u1
        const ulonglong2 W  = Wp [j * U2];
        const ulonglong2 DW = DWp[j * U2];

#pragma unroll
        for (int bb = 0; bb < TBT; bb++) {
            const ulonglong2 L = LNp[bb * D2 + j];   // .x = {l0,l1}, .y = {nmf0,nmf1}
            ublock(P.x, L.x, L.y, DW.x, W.x, acc[bb][0]);   // u0
            ublock(P.y, L.x, L.y, DW.y, W.y, acc[bb][1]);   // u1
        }
    }

    float* o = out + (size_t)b0 * U + 2 * up;
#pragma unroll
    for (int bb = 0; bb < TBT; bb++) {
        float a0, a1;
        unpack2(acc[bb][0], a0, a1);
        atomicAdd(o + bb * U, a0 + a1);
        unpack2(acc[bb][1], a0, a1);
        atomicAdd(o + bb * U + 1, a0 + a1);
    }
}

// ---------------- Generic fallback (only if shapes differ) ----------------
__global__ void fallback_kernel(const float* __restrict__ x,
                                const float* __restrict__ w,
                                const float* __restrict__ p,
                                const float* __restrict__ bias,
                                float* __restrict__ out,
                                int B, int D, int U) {
    int i = blockIdx.x * blockDim.x + threadIdx.x;
    if (i >= B * U) return;
    int b = i / U, u = i % U;
    float s = 0.f;
    for (int d = 0; d < D; d++) {
        float xe = x[b * D + d] + EPS;
        float pv = p[d * U + u];
        float ap = powf(fabsf(xe), pv);
        bool odd = (fmodf(pv, 2.f) != 0.f);
        float sv = (odd && xe < 0.f) ? -ap : ap;
        s += w[d * U + u] * sv;
    }
    out[i] = s + bias[u];
}

// ---------------- Launch ----------------
extern "C" void kernel_launch(void* const* d_in, const int* in_sizes, int n_in,
                              void* d_out, int out_size) {
    const float* x    = (const float*)d_in[0];
    const float* w    = (const float*)d_in[1];
    const float* p    = (const float*)d_in[2];
    const float* bias = (const float*)d_in[3];
    float* out        = (float*)d_out;

    const int U = in_sizes[3];            // 512
    const int D = in_sizes[1] / U;        // 512
    const int B = in_sizes[0] / D;        // 1024

    if (U == 512 && D == 512 && B == 1024) {
        const int nLN4 = B * D / 2;          // 262144
        const int nPW  = (D / 2) * (U / 2);  // 65536
        const int nOut = out_size;           // 524288
        int nmax = nLN4 > nPW ? nLN4 : nPW;
        if (nOut > nmax) nmax = nOut;
        prep_kernel<<<(nmax + 255) / 256, 256>>>(x, w, p, bias, out,
                                                 nLN4, nPW, nOut, D, U);

        // grid: (B/TBT, U2/THREADS, DSPLIT) = (128, 2, 16) = 4096 blocks
        dim3 grid(B / TBT, (U / 2) / THREADS, DSPLIT);
        power_layer_kernel<512, 512><<<grid, THREADS>>>(out);
    } else {
        int n = B * U;
        fallback_kernel<<<(n + 255) / 256, 256>>>(x, w, p, bias, out, B, D, U);
    }
}

// round 15
// speedup vs baseline: 1.6086x; 1.6086x over previous
#include <cuda_runtime.h>
#include <cuda_bf16.h>
#include <math.h>

#define EPS 1e-9f

static constexpr int BMAX = 1024;
static constexpr int DMAX = 512;
static constexpr int UMAX = 512;

typedef unsigned long long ull;

// Scratch (device globals). d-pair-major layouts, consumed as ulonglong2:
__device__ float4 g_LN4[BMAX * DMAX / 2];        // {l0, l1, nmf0, nmf1} per (b, d-pair)
__device__ float4 g_P4 [DMAX / 2 * UMAX / 2];    // {p(d0,u0), p(d1,u0), p(d0,u1), p(d1,u1)}
__device__ float4 g_W4 [DMAX / 2 * UMAX / 2];    // same layout for w
__device__ float4 g_DW4[DMAX / 2 * UMAX / 2];    // same layout: odd(p) ? -2w : 0

// ---------------- f32x2 helpers (R12-proven form: values in C ull vars,
// single-instruction asm, ptxas keeps pairs aligned -> true FFMA2/FMUL2) ----
__device__ __forceinline__ void unpack2(ull p, float& a, float& b) {
    asm("mov.b64 {%0, %1}, %2;" : "=f"(a), "=f"(b) : "l"(p));
}
__device__ __forceinline__ ull pack2(float a, float b) {
    ull r; asm("mov.b64 %0, {%1, %2};" : "=l"(r) : "f"(a), "f"(b)); return r;
}
__device__ __forceinline__ ull mul2(ull a, ull b) {
    ull r; asm("mul.rn.f32x2 %0, %1, %2;" : "=l"(r) : "l"(a), "l"(b)); return r;
}
__device__ __forceinline__ ull fma2(ull a, ull b, ull c) {
    ull r; asm("fma.rn.f32x2 %0, %1, %2, %3;" : "=l"(r) : "l"(a), "l"(b), "l"(c)); return r;
}
__device__ __forceinline__ float ex2(float x) {
    float r; asm("ex2.approx.f32 %0, %1;" : "=f"(r) : "f"(x)); return r;
}

// ---------------- Fused prepass (also inits out = bias) ----------------
__global__ void prep_kernel(const float* __restrict__ x,
                            const float* __restrict__ w,
                            const float* __restrict__ p,
                            const float* __restrict__ bias,
                            float* __restrict__ out,
                            int nLN4, int nPW, int nOut, int D, int U) {
    int i = blockIdx.x * blockDim.x + threadIdx.x;
    const int D2 = D >> 1, U2 = U >> 1;
    if (i < nLN4) {                       // i = b * D2 + dp
        int b  = i / D2;
        int dp = i - b * D2;
        float xe0 = x[b * D + 2 * dp]     + EPS;
        float xe1 = x[b * D + 2 * dp + 1] + EPS;
        float4 v;
        v.x = log2f(fabsf(xe0));
        v.y = log2f(fabsf(xe1));
        v.z = (xe0 < 0.f) ? 1.f : 0.f;
        v.w = (xe1 < 0.f) ? 1.f : 0.f;
        g_LN4[i] = v;
    }
    if (i < nPW) {                        // i = dp * U2 + up
        int dp = i / U2;
        int up = i - dp * U2;
        int base = (2 * dp) * U + 2 * up;
        float p00 = p[base],     p01 = p[base + 1];
        float p10 = p[base + U], p11 = p[base + U + 1];
        float w00 = w[base],     w01 = w[base + 1];
        float w10 = w[base + U], w11 = w[base + U + 1];
        g_P4[i] = make_float4(p00, p10, p01, p11);   // {d0u0, d1u0, d0u1, d1u1}
        g_W4[i] = make_float4(w00, w10, w01, w11);
        float dw00 = (fmodf(p00, 2.f) != 0.f) ? -2.f * w00 : 0.f;
        float dw10 = (fmodf(p10, 2.f) != 0.f) ? -2.f * w10 : 0.f;
        float dw01 = (fmodf(p01, 2.f) != 0.f) ? -2.f * w01 : 0.f;
        float dw11 = (fmodf(p11, 2.f) != 0.f) ? -2.f * w11 : 0.f;
        g_DW4[i] = make_float4(dw00, dw10, dw01, dw11);
    }
    if (i < nOut) out[i] = bias[i % U];
}

// ---------------- Main kernel (compile-time shapes, fully unrolled, f32x2) ----------------
// upt=2, TBT=8, DSPLIT=16. Operands loaded as ulonglong2: pairs arrive
// pre-packed from LDG.128 (no pack MOVs).
static constexpr int TBT     = 8;
static constexpr int THREADS = 128;
static constexpr int DSPLIT  = 16;

template <int D, int U>
__global__ __launch_bounds__(THREADS, 7)
void power_layer_kernel(float* __restrict__ out) {
    constexpr int U2  = U / 2;        // 256 u-pairs
    constexpr int D2  = D / 2;        // 256 d-pairs
    constexpr int nDP = D2 / DSPLIT;  // 16 d-pairs per block

    const int up  = blockIdx.y * THREADS + threadIdx.x;   // u-pair index
    const int b0  = blockIdx.x * TBT;
    const int dp0 = blockIdx.z * nDP;

    const ulonglong2* __restrict__ Pp  = (const ulonglong2*)(g_P4  + dp0 * U2 + up);
    const ulonglong2* __restrict__ Wp  = (const ulonglong2*)(g_W4  + dp0 * U2 + up);
    const ulonglong2* __restrict__ DWp = (const ulonglong2*)(g_DW4 + dp0 * U2 + up);
    const ulonglong2* __restrict__ LNp = (const ulonglong2*)(g_LN4 + (size_t)b0 * D2 + dp0);

    ull acc[TBT][2];
#pragma unroll
    for (int bb = 0; bb < TBT; bb++) { acc[bb][0] = 0ull; acc[bb][1] = 0ull; }

#pragma unroll
    for (int j = 0; j < nDP; j++) {
        // Immediate-offset LDG.128s; .x/.y are pre-packed f32x2 pairs.
        const ulonglong2 P  = Pp [j * U2];   // .x = {p(d0,u0),p(d1,u0)}, .y = u1
        const ulonglong2 W  = Wp [j * U2];
        const ulonglong2 DW = DWp[j * U2];

#pragma unroll
        for (int bb = 0; bb < TBT; bb++) {
            const ulonglong2 L = LNp[bb * D2 + j];   // .x = {l0,l1}, .y = {nmf0,nmf1}

            // u0: e = p.*l; v = 2^e; ws = nm.*dw + w; acc += ws.*v
            {
                ull e = mul2(P.x, L.x);
                float e0, e1; unpack2(e, e0, e1);
                ull v  = pack2(ex2(e0), ex2(e1));
                ull ws = fma2(L.y, DW.x, W.x);
                acc[bb][0] = fma2(ws, v, acc[bb][0]);
            }
            // u1
            {
                ull e = mul2(P.y, L.x);
                float e0, e1; unpack2(e, e0, e1);
                ull v  = pack2(ex2(e0), ex2(e1));
                ull ws = fma2(L.y, DW.y, W.y);
                acc[bb][1] = fma2(ws, v, acc[bb][1]);
            }
        }
    }

    float* o = out + (size_t)b0 * U + 2 * up;
#pragma unroll
    for (int bb = 0; bb < TBT; bb++) {
        float a0, a1;
        unpack2(acc[bb][0], a0, a1);
        atomicAdd(o + bb * U, a0 + a1);
        unpack2(acc[bb][1], a0, a1);
        atomicAdd(o + bb * U + 1, a0 + a1);
    }
}

// ---------------- Generic fallback (only if shapes differ) ----------------
__global__ void fallback_kernel(const float* __restrict__ x,
                                const float* __restrict__ w,
                                const float* __restrict__ p,
                                const float* __restrict__ bias,
                                float* __restrict__ out,
                                int B, int D, int U) {
    int i = blockIdx.x * blockDim.x + threadIdx.x;
    if (i >= B * U) return;
    int b = i / U, u = i % U;
    float s = 0.f;
    for (int d = 0; d < D; d++) {
        float xe = x[b * D + d] + EPS;
        float pv = p[d * U + u];
        float ap = powf(fabsf(xe), pv);
        bool odd = (fmodf(pv, 2.f) != 0.f);
        float sv = (odd && xe < 0.f) ? -ap : ap;
        s += w[d * U + u] * sv;
    }
    out[i] = s + bias[u];
}

// ---------------- Launch ----------------
extern "C" void kernel_launch(void* const* d_in, const int* in_sizes, int n_in,
                              void* d_out, int out_size) {
    const float* x    = (const float*)d_in[0];
    const float* w    = (const float*)d_in[1];
    const float* p    = (const float*)d_in[2];
    const float* bias = (const float*)d_in[3];
    float* out        = (float*)d_out;

    const int U = in_sizes[3];            // 512
    const int D = in_sizes[1] / U;        // 512
    const int B = in_sizes[0] / D;        // 1024

    if (U == 512 && D == 512 && B == 1024) {
        const int nLN4 = B * D / 2;          // 262144
        const int nPW  = (D / 2) * (U / 2);  // 65536
        const int nOut = out_size;           // 524288
        int nmax = nLN4 > nPW ? nLN4 : nPW;
        if (nOut > nmax) nmax = nOut;
        prep_kernel<<<(nmax + 255) / 256, 256>>>(x, w, p, bias, out,
                                                 nLN4, nPW, nOut, D, U);

        // grid: (B/TBT, U2/THREADS, DSPLIT) = (128, 2, 16) = 4096 blocks
        dim3 grid(B / TBT, (U / 2) / THREADS, DSPLIT);
        power_layer_kernel<512, 512><<<grid, THREADS>>>(out);
    } else {
        int n = B * U;
        fallback_kernel<<<(n + 255) / 256, 256>>>(x, w, p, bias, out, B, D, U);
    }
}